// round 12
// baseline (speedup 1.0000x reference)
#include <cuda_runtime.h>
#include <cuda_bf16.h>
#include <cuda_fp16.h>
#include <cuda_fp8.h>
#include <cstdint>

// Problem constants
#define Bsz 16
#define Sq 2048
#define Hd 1024
#define NSP 64
#define NROWS (Bsz * NSP)      // 1024
#define NC 4096
#define ARC_SCALE 30.0f
#define COS_M 0.8775825618903728f
#define SIN_M 0.479425538604203f
#define TH_C (-0.8775825618903728f)
#define MM_C 0.2397127693021015f
#define LN_EPS 1e-7f
#define FP8_SCALE 16.0f
#define INV_S2 (1.0f / 256.0f)

// ---------------- scratch (no allocations allowed) ----------------
__device__ __nv_fp8_storage_t g_emb[NROWS * Hd];
__device__ __nv_fp8_storage_t g_w[NC * Hd];
__device__ float g_rowsum[NROWS];
__device__ float g_lablogit[NROWS];

// ---------------- reductions ----------------
// 256-thread block reduce (for gemm/finish)
__device__ __forceinline__ float blockReduceSum(float v, float* sbuf) {
    int lane = threadIdx.x & 31, wid = threadIdx.x >> 5;
#pragma unroll
    for (int o = 16; o; o >>= 1) v += __shfl_down_sync(0xffffffffu, v, o);
    if (lane == 0) sbuf[wid] = v;
    __syncthreads();
    if (wid == 0) {
        v = (lane < 8) ? sbuf[lane] : 0.f;
#pragma unroll
        for (int o = 4; o; o >>= 1) v += __shfl_down_sync(0xffffffffu, v, o);
        if (lane == 0) sbuf[0] = v;
    }
    __syncthreads();
    float r = sbuf[0];
    __syncthreads();
    return r;
}

// 512-thread block reduce
__device__ __forceinline__ float blockReduceSum512(float v, float* sbuf) {
    int lane = threadIdx.x & 31, wid = threadIdx.x >> 5;   // wid 0..15
#pragma unroll
    for (int o = 16; o; o >>= 1) v += __shfl_down_sync(0xffffffffu, v, o);
    if (lane == 0) sbuf[wid] = v;
    __syncthreads();
    if (wid == 0) {
        v = (lane < 16) ? sbuf[lane] : 0.f;
#pragma unroll
        for (int o = 8; o; o >>= 1) v += __shfl_down_sync(0xffffffffu, v, o);
        if (lane == 0) sbuf[0] = v;
    }
    __syncthreads();
    float r = sbuf[0];
    __syncthreads();
    return r;
}

// per-half (256-thread) reduce inside a 512-thread block; both halves get
// their own sum. sbuf must hold >= 18 floats.
__device__ __forceinline__ float halfReduceSum(float v, float* sbuf) {
    int lane = threadIdx.x & 31, wid = threadIdx.x >> 5;   // wid 0..15
#pragma unroll
    for (int o = 16; o; o >>= 1) v += __shfl_down_sync(0xffffffffu, v, o);
    if (lane == 0) sbuf[wid] = v;
    __syncthreads();
    float r = (lane < 8) ? sbuf[(wid & 8) + lane] : 0.f;
#pragma unroll
    for (int o = 4; o; o >>= 1) r += __shfl_down_sync(0xffffffffu, r, o);
    if (lane == 0) sbuf[16 + (wid >> 3)] = r;
    __syncthreads();
    float res = sbuf[16 + (wid >> 3)];
    __syncthreads();
    return res;
}

__device__ __forceinline__ uchar4 pack_fp8x4(float a, float b, float c, float d) {
    uchar4 o;
    o.x = __nv_cvt_float_to_fp8(a, __NV_SATFINITE, __NV_E4M3);
    o.y = __nv_cvt_float_to_fp8(b, __NV_SATFINITE, __NV_E4M3);
    o.z = __nv_cvt_float_to_fp8(c, __NV_SATFINITE, __NV_E4M3);
    o.w = __nv_cvt_float_to_fp8(d, __NV_SATFINITE, __NV_E4M3);
    return o;
}

// ---------------- K1: prep, 512 threads ----------------
// Blocks [0, NROWS): span mean+LN+L2, two 256-thread time-slices per span.
// Blocks [NROWS, NROWS + NC/2): weight L2, 2 rows per block (one per half).
__global__ __launch_bounds__(512) void prep_kernel(
    const float* __restrict__ enc, const float* __restrict__ gamma,
    const float* __restrict__ beta, const int* __restrict__ heads,
    const int* __restrict__ tails, const float* __restrict__ w) {
    __shared__ float sbuf[18];
    __shared__ float4 part[256];
    int tid = threadIdx.x;
    int half = tid >> 8;       // 0 or 1
    int ht = tid & 255;        // h-chunk (float4) index

    if (blockIdx.x < NROWS) {
        int row = blockIdx.x;
        int b = row >> 6;
        int head = heads[row], tail = tails[row];
        float inv_len = 1.f / (float)(tail - head);

        const float4* base = (const float4*)enc + (size_t)b * Sq * (Hd / 4) + ht;
        // this slice accumulates t = head+half, head+half+2, ... (pipelined)
        float4 acc = make_float4(0.f, 0.f, 0.f, 0.f);
        int t = head + half;
        if (t < tail) {
            float4 v = base[(size_t)t * (Hd / 4)];
            for (t += 2; t < tail; t += 2) {
                float4 vn = base[(size_t)t * (Hd / 4)];
                acc.x += v.x; acc.y += v.y; acc.z += v.z; acc.w += v.w;
                v = vn;
            }
            acc.x += v.x; acc.y += v.y; acc.z += v.z; acc.w += v.w;
        }
        // combine the two slices
        if (half == 1) part[ht] = acc;
        __syncthreads();
        float x0 = 0.f, x1 = 0.f, x2 = 0.f, x3 = 0.f;
        if (half == 0) {
            float4 p = part[ht];
            x0 = (acc.x + p.x) * inv_len;
            x1 = (acc.y + p.y) * inv_len;
            x2 = (acc.z + p.z) * inv_len;
            x3 = (acc.w + p.w) * inv_len;
        }
        __syncthreads();

        float s1 = blockReduceSum512(x0 + x1 + x2 + x3, sbuf);
        float s2 = blockReduceSum512(x0 * x0 + x1 * x1 + x2 * x2 + x3 * x3, sbuf);
        float mu = s1 * (1.f / Hd);
        float var = s2 * (1.f / Hd) - mu * mu;
        float rs = rsqrtf(var + LN_EPS);

        float y0 = 0.f, y1 = 0.f, y2 = 0.f, y3 = 0.f;
        if (half == 0) {
            float4 gm = ((const float4*)gamma)[ht];
            float4 bt = ((const float4*)beta)[ht];
            y0 = (x0 - mu) * rs * gm.x + bt.x;
            y1 = (x1 - mu) * rs * gm.y + bt.y;
            y2 = (x2 - mu) * rs * gm.z + bt.z;
            y3 = (x3 - mu) * rs * gm.w + bt.w;
        }
        float s3 = blockReduceSum512(y0 * y0 + y1 * y1 + y2 * y2 + y3 * y3, sbuf);
        float sc = FP8_SCALE / fmaxf(sqrtf(s3), 1e-12f);

        if (half == 0) {
            ((uchar4*)(g_emb + (size_t)row * Hd))[ht] =
                pack_fp8x4(y0 * sc, y1 * sc, y2 * sc, y3 * sc);
        }
        if (tid == 0) g_rowsum[row] = 0.f;
    } else {
        int row = (blockIdx.x - NROWS) * 2 + half;
        float4 v = ((const float4*)w)[(size_t)row * (Hd / 4) + ht];
        float s = halfReduceSum(v.x * v.x + v.y * v.y + v.z * v.z + v.w * v.w, sbuf);
        float sc = FP8_SCALE / fmaxf(sqrtf(s), 1e-12f);
        ((uchar4*)(g_w + (size_t)row * Hd))[ht] =
            pack_fp8x4(v.x * sc, v.y * sc, v.z * sc, v.w * sc);
    }
}

// ---------------- K2: FP8 GEMM (f16 accumulate), 2 CTAs/SM ------------------
#define BM 128
#define BN 128
#define BK 64
#define LDB 80
#define NSTG 4
#define NKT (Hd / BK)          // 16
#define STG_BYTES ((BM + BN) * LDB)    // 20480
#define DSMEM_BYTES (NSTG * STG_BYTES) // 81920
#define NTHR 256

__device__ __forceinline__ void cp16(uint32_t smem_dst, const void* gsrc) {
    asm volatile("cp.async.cg.shared.global [%0], [%1], 16;\n" ::"r"(smem_dst), "l"(gsrc));
}

__device__ __forceinline__ void cp_stage(uint32_t stage_base, int bm0, int bn0,
                                         int kt, int tid) {
    int k0 = kt * BK;
    uint32_t a_base = stage_base;
    uint32_t b_base = stage_base + BM * LDB;
#pragma unroll
    for (int i = 0; i < 2; i++) {
        int idx = tid + i * NTHR;
        int r = idx >> 2, c = idx & 3;
        cp16(a_base + r * LDB + c * 16,
             g_emb + (size_t)(bm0 + r) * Hd + k0 + c * 16);
    }
#pragma unroll
    for (int i = 0; i < 2; i++) {
        int idx = tid + i * NTHR;
        int r = idx >> 2, c = idx & 3;
        cp16(b_base + r * LDB + c * 16,
             g_w + (size_t)(bn0 + r) * Hd + k0 + c * 16);
    }
    asm volatile("cp.async.commit_group;\n" ::: "memory");
}

__device__ __forceinline__ void ldmx4(uint32_t addr, uint32_t& r0, uint32_t& r1,
                                      uint32_t& r2, uint32_t& r3) {
    asm volatile("ldmatrix.sync.aligned.m8n8.x4.shared.b16 {%0,%1,%2,%3}, [%4];"
                 : "=r"(r0), "=r"(r1), "=r"(r2), "=r"(r3) : "r"(addr));
}

__global__ __launch_bounds__(NTHR, 2) void gemm_fused(const int* __restrict__ labels) {
    extern __shared__ __align__(16) char smem[];
    __shared__ float rowacc[BM];
    __shared__ int slab[BM];

    int tid = threadIdx.x, wid = tid >> 5, lane = tid & 31;
    int bn0 = blockIdx.x * BN, bm0 = blockIdx.y * BM;
    int wm = (wid >> 2) * 64;       // 2 warp rows in M
    int wn = (wid & 3) * 32;        // 4 warp cols in N
    int fr = lane >> 2, fc = (lane & 3) * 2;

    if (tid < BM) {
        rowacc[tid] = 0.f;
        slab[tid] = labels[bm0 + tid];
    }

    uint32_t smem_base = (uint32_t)__cvta_generic_to_shared(smem);
    uint32_t aBase = smem_base + (wm + (lane & 15)) * LDB + ((lane >> 4) << 4);
    uint32_t bBase = smem_base + BM * LDB +
        (wn + ((lane >> 4) << 3) + (lane & 7)) * LDB + (((lane >> 3) & 1) << 4);

    uint32_t acc[4][4][2];
#pragma unroll
    for (int i = 0; i < 4; i++)
#pragma unroll
        for (int j = 0; j < 4; j++) {
            acc[i][j][0] = 0u;
            acc[i][j][1] = 0u;
        }

#pragma unroll
    for (int s = 0; s < NSTG - 1; s++)
        cp_stage(smem_base + s * STG_BYTES, bm0, bn0, s, tid);

#pragma unroll 1
    for (int kt = 0; kt < NKT; kt++) {
        asm volatile("cp.async.wait_group %0;\n" ::"n"(NSTG - 2) : "memory");
        __syncthreads();

        if (kt + NSTG - 1 < NKT)
            cp_stage(smem_base + ((kt + NSTG - 1) % NSTG) * STG_BYTES, bm0, bn0,
                     kt + NSTG - 1, tid);
        else
            asm volatile("cp.async.commit_group;\n" ::: "memory");

        uint32_t soff = (uint32_t)((kt % NSTG) * STG_BYTES);

#pragma unroll
        for (int ks = 0; ks < 2; ks++) {
            uint32_t a[4][4], b[4][2];
#pragma unroll
            for (int mi = 0; mi < 4; mi++)
                ldmx4(aBase + soff + mi * (16 * LDB) + ks * 32,
                      a[mi][0], a[mi][1], a[mi][2], a[mi][3]);
#pragma unroll
            for (int p = 0; p < 2; p++)
                ldmx4(bBase + soff + p * (16 * LDB) + ks * 32,
                      b[2 * p][0], b[2 * p][1], b[2 * p + 1][0], b[2 * p + 1][1]);
#pragma unroll
            for (int mi = 0; mi < 4; mi++)
#pragma unroll
                for (int ni = 0; ni < 4; ni++) {
                    uint32_t* c = acc[mi][ni];
                    asm volatile(
                        "mma.sync.aligned.m16n8k32.row.col.f16.e4m3.e4m3.f16 "
                        "{%0,%1}, {%2,%3,%4,%5}, {%6,%7}, {%0,%1};"
                        : "+r"(c[0]), "+r"(c[1])
                        : "r"(a[mi][0]), "r"(a[mi][1]), "r"(a[mi][2]), "r"(a[mi][3]),
                          "r"(b[ni][0]), "r"(b[ni][1]));
                }
        }
        __syncthreads();
    }

    // ---- fused epilogue: arcface margin + shifted sum-exp ----
#pragma unroll
    for (int mi = 0; mi < 4; mi++) {
        int lr0 = wm + mi * 16 + fr;
        int lr1 = lr0 + 8;
        int lab0 = slab[lr0], lab1 = slab[lr1];
        float s0 = 0.f, s1 = 0.f;
#pragma unroll
        for (int ni = 0; ni < 4; ni++) {
            int gc = bn0 + wn + ni * 8 + fc;
            float2 lo = __half22float2(*(const __half2*)&acc[mi][ni][0]);
            float2 hi = __half22float2(*(const __half2*)&acc[mi][ni][1]);
            float cvals[4] = {lo.x, lo.y, hi.x, hi.y};
#pragma unroll
            for (int e = 0; e < 2; e++) {
                int col = gc + e;
                {
                    float cv = cvals[e] * INV_S2;
                    float lg = ARC_SCALE * cv - ARC_SCALE;
                    if (col == lab0) {
                        float sn = sqrtf(fmaxf(0.f, 1.f - cv * cv));
                        float phi = cv * COS_M - sn * SIN_M;
                        if (!(cv > TH_C)) phi = cv - MM_C;
                        lg = ARC_SCALE * phi - ARC_SCALE;
                        g_lablogit[bm0 + lr0] = ARC_SCALE * phi;
                    }
                    s0 += __expf(lg);
                }
                {
                    float cv = cvals[2 + e] * INV_S2;
                    float lg = ARC_SCALE * cv - ARC_SCALE;
                    if (col == lab1) {
                        float sn = sqrtf(fmaxf(0.f, 1.f - cv * cv));
                        float phi = cv * COS_M - sn * SIN_M;
                        if (!(cv > TH_C)) phi = cv - MM_C;
                        lg = ARC_SCALE * phi - ARC_SCALE;
                        g_lablogit[bm0 + lr1] = ARC_SCALE * phi;
                    }
                    s1 += __expf(lg);
                }
            }
        }
        s0 += __shfl_down_sync(0xffffffffu, s0, 1);
        s0 += __shfl_down_sync(0xffffffffu, s0, 2);
        s1 += __shfl_down_sync(0xffffffffu, s1, 1);
        s1 += __shfl_down_sync(0xffffffffu, s1, 2);
        if ((lane & 3) == 0) {
            atomicAdd(&rowacc[lr0], s0);
            atomicAdd(&rowacc[lr1], s1);
        }
    }
    __syncthreads();
    if (tid < BM) atomicAdd(&g_rowsum[bm0 + tid], rowacc[tid]);
}

// ---------------- K3: final mean over rows ----------------
__global__ __launch_bounds__(256) void finish_kernel(float* __restrict__ out) {
    __shared__ float sbuf[8];
    float s = 0.f;
    for (int i = threadIdx.x; i < NROWS; i += 256)
        s += ARC_SCALE + logf(g_rowsum[i]) - g_lablogit[i];
    float tot = blockReduceSum(s, sbuf);
    if (threadIdx.x == 0) out[0] = tot * (1.f / NROWS);
}

// ---------------- launch ----------------
extern "C" void kernel_launch(void* const* d_in, const int* in_sizes, int n_in,
                              void* d_out, int out_size) {
    const float* enc = (const float*)d_in[0];
    const float* gamma = (const float*)d_in[1];
    const float* beta = (const float*)d_in[2];
    const float* arc_w = (const float*)d_in[3];
    const int* heads = (const int*)d_in[4];
    const int* tails = (const int*)d_in[5];
    const int* labels = (const int*)d_in[6];
    float* out = (float*)d_out;

    static int configured = 0;
    if (!configured) {
        cudaFuncSetAttribute(gemm_fused, cudaFuncAttributeMaxDynamicSharedMemorySize,
                             DSMEM_BYTES);
        configured = 1;
    }

    prep_kernel<<<NROWS + NC / 2, 512>>>(enc, gamma, beta, heads, tails, arc_w);
    gemm_fused<<<dim3(NC / BN, NROWS / BM), NTHR, DSMEM_BYTES>>>(labels);
    finish_kernel<<<1, 256>>>(out);
}

// round 13
// speedup vs baseline: 1.0293x; 1.0293x over previous
#include <cuda_runtime.h>
#include <cuda_bf16.h>
#include <cuda_fp16.h>
#include <cuda_fp8.h>
#include <cstdint>

// Problem constants
#define Bsz 16
#define Sq 2048
#define Hd 1024
#define NSP 64
#define NROWS (Bsz * NSP)      // 1024
#define NC 4096
#define ARC_SCALE 30.0f
#define COS_M 0.8775825618903728f
#define SIN_M 0.479425538604203f
#define TH_C (-0.8775825618903728f)
#define MM_C 0.2397127693021015f
#define LN_EPS 1e-7f
#define FP8_SCALE 16.0f
#define INV_S2 (1.0f / 256.0f)

// ---------------- scratch (no allocations allowed) ----------------
__device__ __nv_fp8_storage_t g_emb[NROWS * Hd];
__device__ __nv_fp8_storage_t g_w[NC * Hd];
__device__ float g_rowsum[NROWS];
__device__ float g_lablogit[NROWS];

// ---------------- reductions ----------------
__device__ __forceinline__ float blockReduceSum(float v, float* sbuf) {
    int lane = threadIdx.x & 31, wid = threadIdx.x >> 5;
#pragma unroll
    for (int o = 16; o; o >>= 1) v += __shfl_down_sync(0xffffffffu, v, o);
    if (lane == 0) sbuf[wid] = v;
    __syncthreads();
    if (wid == 0) {
        v = (lane < 8) ? sbuf[lane] : 0.f;
#pragma unroll
        for (int o = 4; o; o >>= 1) v += __shfl_down_sync(0xffffffffu, v, o);
        if (lane == 0) sbuf[0] = v;
    }
    __syncthreads();
    float r = sbuf[0];
    __syncthreads();
    return r;
}

__device__ __forceinline__ uchar4 pack_fp8x4(float a, float b, float c, float d) {
    uchar4 o;
    o.x = __nv_cvt_float_to_fp8(a, __NV_SATFINITE, __NV_E4M3);
    o.y = __nv_cvt_float_to_fp8(b, __NV_SATFINITE, __NV_E4M3);
    o.z = __nv_cvt_float_to_fp8(c, __NV_SATFINITE, __NV_E4M3);
    o.w = __nv_cvt_float_to_fp8(d, __NV_SATFINITE, __NV_E4M3);
    return o;
}

// ---------------- K1: fused prep (R11-proven, block-per-task) ---------------
__global__ __launch_bounds__(256) void prep_kernel(
    const float* __restrict__ enc, const float* __restrict__ gamma,
    const float* __restrict__ beta, const int* __restrict__ heads,
    const int* __restrict__ tails, const float* __restrict__ w) {
    __shared__ float sbuf[8];
    int tid = threadIdx.x;

    if (blockIdx.x < NROWS) {
        int row = blockIdx.x;
        int b = row >> 6;
        int head = heads[row], tail = tails[row];
        float inv_len = 1.f / (float)(tail - head);

        const float4* base = (const float4*)enc + (size_t)b * Sq * (Hd / 4) + tid;
        float4 acc = make_float4(0.f, 0.f, 0.f, 0.f);
        float4 v = base[(size_t)head * (Hd / 4)];
        for (int t = head + 1; t < tail; ++t) {
            float4 vn = base[(size_t)t * (Hd / 4)];
            acc.x += v.x; acc.y += v.y; acc.z += v.z; acc.w += v.w;
            v = vn;
        }
        acc.x += v.x; acc.y += v.y; acc.z += v.z; acc.w += v.w;

        float x0 = acc.x * inv_len, x1 = acc.y * inv_len;
        float x2 = acc.z * inv_len, x3 = acc.w * inv_len;

        float s1 = blockReduceSum(x0 + x1 + x2 + x3, sbuf);
        float s2 = blockReduceSum(x0 * x0 + x1 * x1 + x2 * x2 + x3 * x3, sbuf);
        float mu = s1 * (1.f / Hd);
        float var = s2 * (1.f / Hd) - mu * mu;
        float rs = rsqrtf(var + LN_EPS);

        float4 gm = ((const float4*)gamma)[tid];
        float4 bt = ((const float4*)beta)[tid];
        float y0 = (x0 - mu) * rs * gm.x + bt.x;
        float y1 = (x1 - mu) * rs * gm.y + bt.y;
        float y2 = (x2 - mu) * rs * gm.z + bt.z;
        float y3 = (x3 - mu) * rs * gm.w + bt.w;

        float s3 = blockReduceSum(y0 * y0 + y1 * y1 + y2 * y2 + y3 * y3, sbuf);
        float sc = FP8_SCALE / fmaxf(sqrtf(s3), 1e-12f);

        ((uchar4*)(g_emb + (size_t)row * Hd))[tid] =
            pack_fp8x4(y0 * sc, y1 * sc, y2 * sc, y3 * sc);
        if (tid == 0) g_rowsum[row] = 0.f;
    } else {
        int row = blockIdx.x - NROWS;
        float4 v = ((const float4*)w)[(size_t)row * (Hd / 4) + tid];
        float s = blockReduceSum(v.x * v.x + v.y * v.y + v.z * v.z + v.w * v.w, sbuf);
        float sc = FP8_SCALE / fmaxf(sqrtf(s), 1e-12f);
        ((uchar4*)(g_w + (size_t)row * Hd))[tid] =
            pack_fp8x4(v.x * sc, v.y * sc, v.z * sc, v.w * sc);
    }
}

// ---------------- K2: FP8 GEMM (f16 acc), 3 CTAs/SM -------------------------
#define BM 128
#define BN 128
#define BK 64
#define LDB 80
#define NSTG 3
#define NKT (Hd / BK)          // 16
#define STG_BYTES ((BM + BN) * LDB)    // 20480
#define DSMEM_BYTES (NSTG * STG_BYTES) // 61440
#define NTHR 256

__device__ __forceinline__ void cp16(uint32_t smem_dst, const void* gsrc) {
    asm volatile("cp.async.cg.shared.global [%0], [%1], 16;\n" ::"r"(smem_dst), "l"(gsrc));
}

__device__ __forceinline__ void cp_stage(uint32_t stage_base, int bm0, int bn0,
                                         int kt, int tid) {
    int k0 = kt * BK;
    uint32_t a_base = stage_base;
    uint32_t b_base = stage_base + BM * LDB;
#pragma unroll
    for (int i = 0; i < 2; i++) {
        int idx = tid + i * NTHR;
        int r = idx >> 2, c = idx & 3;
        cp16(a_base + r * LDB + c * 16,
             g_emb + (size_t)(bm0 + r) * Hd + k0 + c * 16);
    }
#pragma unroll
    for (int i = 0; i < 2; i++) {
        int idx = tid + i * NTHR;
        int r = idx >> 2, c = idx & 3;
        cp16(b_base + r * LDB + c * 16,
             g_w + (size_t)(bn0 + r) * Hd + k0 + c * 16);
    }
    asm volatile("cp.async.commit_group;\n" ::: "memory");
}

__device__ __forceinline__ void ldmx4(uint32_t addr, uint32_t& r0, uint32_t& r1,
                                      uint32_t& r2, uint32_t& r3) {
    asm volatile("ldmatrix.sync.aligned.m8n8.x4.shared.b16 {%0,%1,%2,%3}, [%4];"
                 : "=r"(r0), "=r"(r1), "=r"(r2), "=r"(r3) : "r"(addr));
}

__global__ __launch_bounds__(NTHR, 3) void gemm_fused(const int* __restrict__ labels) {
    extern __shared__ __align__(16) char smem[];
    __shared__ float rowacc[BM];
    __shared__ int slab[BM];

    int tid = threadIdx.x, wid = tid >> 5, lane = tid & 31;
    int bn0 = blockIdx.x * BN, bm0 = blockIdx.y * BM;
    int wm = (wid >> 2) * 64;       // 2 warp rows in M
    int wn = (wid & 3) * 32;        // 4 warp cols in N
    int fr = lane >> 2, fc = (lane & 3) * 2;

    if (tid < BM) {
        rowacc[tid] = 0.f;
        slab[tid] = labels[bm0 + tid];
    }

    uint32_t smem_base = (uint32_t)__cvta_generic_to_shared(smem);
    uint32_t aBase = smem_base + (wm + (lane & 15)) * LDB + ((lane >> 4) << 4);
    uint32_t bBase = smem_base + BM * LDB +
        (wn + ((lane >> 4) << 3) + (lane & 7)) * LDB + (((lane >> 3) & 1) << 4);

    uint32_t acc[4][4][2];
#pragma unroll
    for (int i = 0; i < 4; i++)
#pragma unroll
        for (int j = 0; j < 4; j++) {
            acc[i][j][0] = 0u;
            acc[i][j][1] = 0u;
        }

#pragma unroll
    for (int s = 0; s < NSTG - 1; s++)
        cp_stage(smem_base + s * STG_BYTES, bm0, bn0, s, tid);

#pragma unroll 1
    for (int kt = 0; kt < NKT; kt++) {
        asm volatile("cp.async.wait_group %0;\n" ::"n"(NSTG - 2) : "memory");
        __syncthreads();

        if (kt + NSTG - 1 < NKT)
            cp_stage(smem_base + ((kt + NSTG - 1) % NSTG) * STG_BYTES, bm0, bn0,
                     kt + NSTG - 1, tid);
        else
            asm volatile("cp.async.commit_group;\n" ::: "memory");

        uint32_t soff = (uint32_t)((kt % NSTG) * STG_BYTES);

#pragma unroll
        for (int ks = 0; ks < 2; ks++) {
            uint32_t a[4][4], b[4][2];
#pragma unroll
            for (int mi = 0; mi < 4; mi++)
                ldmx4(aBase + soff + mi * (16 * LDB) + ks * 32,
                      a[mi][0], a[mi][1], a[mi][2], a[mi][3]);
#pragma unroll
            for (int p = 0; p < 2; p++)
                ldmx4(bBase + soff + p * (16 * LDB) + ks * 32,
                      b[2 * p][0], b[2 * p][1], b[2 * p + 1][0], b[2 * p + 1][1]);
#pragma unroll
            for (int mi = 0; mi < 4; mi++)
#pragma unroll
                for (int ni = 0; ni < 4; ni++) {
                    uint32_t* c = acc[mi][ni];
                    asm volatile(
                        "mma.sync.aligned.m16n8k32.row.col.f16.e4m3.e4m3.f16 "
                        "{%0,%1}, {%2,%3,%4,%5}, {%6,%7}, {%0,%1};"
                        : "+r"(c[0]), "+r"(c[1])
                        : "r"(a[mi][0]), "r"(a[mi][1]), "r"(a[mi][2]), "r"(a[mi][3]),
                          "r"(b[ni][0]), "r"(b[ni][1]));
                }
        }
        __syncthreads();
    }

    // ---- fused epilogue: arcface margin + shifted sum-exp ----
#pragma unroll
    for (int mi = 0; mi < 4; mi++) {
        int lr0 = wm + mi * 16 + fr;
        int lr1 = lr0 + 8;
        int lab0 = slab[lr0], lab1 = slab[lr1];
        float s0 = 0.f, s1 = 0.f;
#pragma unroll
        for (int ni = 0; ni < 4; ni++) {
            int gc = bn0 + wn + ni * 8 + fc;
            float2 lo = __half22float2(*(const __half2*)&acc[mi][ni][0]);
            float2 hi = __half22float2(*(const __half2*)&acc[mi][ni][1]);
            float cvals[4] = {lo.x, lo.y, hi.x, hi.y};
#pragma unroll
            for (int e = 0; e < 2; e++) {
                int col = gc + e;
                {
                    float cv = cvals[e] * INV_S2;
                    float lg = ARC_SCALE * cv - ARC_SCALE;
                    if (col == lab0) {
                        float sn = sqrtf(fmaxf(0.f, 1.f - cv * cv));
                        float phi = cv * COS_M - sn * SIN_M;
                        if (!(cv > TH_C)) phi = cv - MM_C;
                        lg = ARC_SCALE * phi - ARC_SCALE;
                        g_lablogit[bm0 + lr0] = ARC_SCALE * phi;
                    }
                    s0 += __expf(lg);
                }
                {
                    float cv = cvals[2 + e] * INV_S2;
                    float lg = ARC_SCALE * cv - ARC_SCALE;
                    if (col == lab1) {
                        float sn = sqrtf(fmaxf(0.f, 1.f - cv * cv));
                        float phi = cv * COS_M - sn * SIN_M;
                        if (!(cv > TH_C)) phi = cv - MM_C;
                        lg = ARC_SCALE * phi - ARC_SCALE;
                        g_lablogit[bm0 + lr1] = ARC_SCALE * phi;
                    }
                    s1 += __expf(lg);
                }
            }
        }
        s0 += __shfl_down_sync(0xffffffffu, s0, 1);
        s0 += __shfl_down_sync(0xffffffffu, s0, 2);
        s1 += __shfl_down_sync(0xffffffffu, s1, 1);
        s1 += __shfl_down_sync(0xffffffffu, s1, 2);
        if ((lane & 3) == 0) {
            atomicAdd(&rowacc[lr0], s0);
            atomicAdd(&rowacc[lr1], s1);
        }
    }
    __syncthreads();
    if (tid < BM) atomicAdd(&g_rowsum[bm0 + tid], rowacc[tid]);
}

// ---------------- K3: final mean over rows ----------------
__global__ __launch_bounds__(256) void finish_kernel(float* __restrict__ out) {
    __shared__ float sbuf[8];
    float s = 0.f;
    for (int i = threadIdx.x; i < NROWS; i += 256)
        s += ARC_SCALE + logf(g_rowsum[i]) - g_lablogit[i];
    float tot = blockReduceSum(s, sbuf);
    if (threadIdx.x == 0) out[0] = tot * (1.f / NROWS);
}

// ---------------- launch ----------------
extern "C" void kernel_launch(void* const* d_in, const int* in_sizes, int n_in,
                              void* d_out, int out_size) {
    const float* enc = (const float*)d_in[0];
    const float* gamma = (const float*)d_in[1];
    const float* beta = (const float*)d_in[2];
    const float* arc_w = (const float*)d_in[3];
    const int* heads = (const int*)d_in[4];
    const int* tails = (const int*)d_in[5];
    const int* labels = (const int*)d_in[6];
    float* out = (float*)d_out;

    static int configured = 0;
    if (!configured) {
        cudaFuncSetAttribute(gemm_fused, cudaFuncAttributeMaxDynamicSharedMemorySize,
                             DSMEM_BYTES);
        configured = 1;
    }

    prep_kernel<<<NROWS + NC, 256>>>(enc, gamma, beta, heads, tails, arc_w);
    gemm_fused<<<dim3(NC / BN, NROWS / BM), NTHR, DSMEM_BYTES>>>(labels);
    finish_kernel<<<1, 256>>>(out);
}

// round 14
// speedup vs baseline: 1.0406x; 1.0110x over previous
#include <cuda_runtime.h>
#include <cuda_bf16.h>
#include <cuda_fp16.h>
#include <cuda_fp8.h>
#include <cstdint>

// Problem constants
#define Bsz 16
#define Sq 2048
#define Hd 1024
#define NSP 64
#define NROWS (Bsz * NSP)      // 1024
#define NC 4096
#define ARC_SCALE 30.0f
#define COS_M 0.8775825618903728f
#define SIN_M 0.479425538604203f
#define TH_C (-0.8775825618903728f)
#define MM_C 0.2397127693021015f
#define LN_EPS 1e-7f
#define FP8_SCALE 16.0f
#define INV_S2 (1.0f / 256.0f)

// ---------------- scratch (no allocations allowed) ----------------
__device__ __nv_fp8_storage_t g_emb[NROWS * Hd];
__device__ __nv_fp8_storage_t g_w[NC * Hd];
__device__ float g_rowsum[NROWS];
__device__ float g_lablogit[NROWS];

// ---------------- reductions ----------------
__device__ __forceinline__ float blockReduceSum(float v, float* sbuf) {
    int lane = threadIdx.x & 31, wid = threadIdx.x >> 5;
#pragma unroll
    for (int o = 16; o; o >>= 1) v += __shfl_down_sync(0xffffffffu, v, o);
    if (lane == 0) sbuf[wid] = v;
    __syncthreads();
    if (wid == 0) {
        v = (lane < 8) ? sbuf[lane] : 0.f;
#pragma unroll
        for (int o = 4; o; o >>= 1) v += __shfl_down_sync(0xffffffffu, v, o);
        if (lane == 0) sbuf[0] = v;
    }
    __syncthreads();
    float r = sbuf[0];
    __syncthreads();
    return r;
}

__device__ __forceinline__ uchar4 pack_fp8x4(float a, float b, float c, float d) {
    uchar4 o;
    o.x = __nv_cvt_float_to_fp8(a, __NV_SATFINITE, __NV_E4M3);
    o.y = __nv_cvt_float_to_fp8(b, __NV_SATFINITE, __NV_E4M3);
    o.z = __nv_cvt_float_to_fp8(c, __NV_SATFINITE, __NV_E4M3);
    o.w = __nv_cvt_float_to_fp8(d, __NV_SATFINITE, __NV_E4M3);
    return o;
}

// ---------------- K1: fused prep (block-per-task, pipelined span loop) ------
__global__ __launch_bounds__(256) void prep_kernel(
    const float* __restrict__ enc, const float* __restrict__ gamma,
    const float* __restrict__ beta, const int* __restrict__ heads,
    const int* __restrict__ tails, const float* __restrict__ w) {
    __shared__ float sbuf[8];
    int tid = threadIdx.x;

    if (blockIdx.x < NROWS) {
        int row = blockIdx.x;
        int b = row >> 6;
        int head = heads[row], tail = tails[row];
        float inv_len = 1.f / (float)(tail - head);

        const float4* base = (const float4*)enc + (size_t)b * Sq * (Hd / 4) + tid;
        float4 acc = make_float4(0.f, 0.f, 0.f, 0.f);
        float4 v = base[(size_t)head * (Hd / 4)];
        for (int t = head + 1; t < tail; ++t) {
            float4 vn = base[(size_t)t * (Hd / 4)];
            acc.x += v.x; acc.y += v.y; acc.z += v.z; acc.w += v.w;
            v = vn;
        }
        acc.x += v.x; acc.y += v.y; acc.z += v.z; acc.w += v.w;

        float x0 = acc.x * inv_len, x1 = acc.y * inv_len;
        float x2 = acc.z * inv_len, x3 = acc.w * inv_len;

        float s1 = blockReduceSum(x0 + x1 + x2 + x3, sbuf);
        float s2 = blockReduceSum(x0 * x0 + x1 * x1 + x2 * x2 + x3 * x3, sbuf);
        float mu = s1 * (1.f / Hd);
        float var = s2 * (1.f / Hd) - mu * mu;
        float rs = rsqrtf(var + LN_EPS);

        float4 gm = ((const float4*)gamma)[tid];
        float4 bt = ((const float4*)beta)[tid];
        float y0 = (x0 - mu) * rs * gm.x + bt.x;
        float y1 = (x1 - mu) * rs * gm.y + bt.y;
        float y2 = (x2 - mu) * rs * gm.z + bt.z;
        float y3 = (x3 - mu) * rs * gm.w + bt.w;

        float s3 = blockReduceSum(y0 * y0 + y1 * y1 + y2 * y2 + y3 * y3, sbuf);
        float sc = FP8_SCALE / fmaxf(sqrtf(s3), 1e-12f);

        ((uchar4*)(g_emb + (size_t)row * Hd))[tid] =
            pack_fp8x4(y0 * sc, y1 * sc, y2 * sc, y3 * sc);
        if (tid == 0) g_rowsum[row] = 0.f;
    } else {
        int row = blockIdx.x - NROWS;
        float4 v = ((const float4*)w)[(size_t)row * (Hd / 4) + tid];
        float s = blockReduceSum(v.x * v.x + v.y * v.y + v.z * v.z + v.w * v.w, sbuf);
        float sc = FP8_SCALE / fmaxf(sqrtf(s), 1e-12f);
        ((uchar4*)(g_w + (size_t)row * Hd))[tid] =
            pack_fp8x4(v.x * sc, v.y * sc, v.z * sc, v.w * sc);
    }
}

// ---------------- K2: FP8 GEMM (f16 accumulate), 2 CTAs/SM, 1 barrier/kt ----
#define BM 128
#define BN 128
#define BK 64
#define LDB 80
#define NSTG 4
#define NKT (Hd / BK)          // 16
#define STG_BYTES ((BM + BN) * LDB)    // 20480
#define DSMEM_BYTES (NSTG * STG_BYTES) // 81920
#define NTHR 256

__device__ __forceinline__ void cp16(uint32_t smem_dst, const void* gsrc) {
    asm volatile("cp.async.cg.shared.global [%0], [%1], 16;\n" ::"r"(smem_dst), "l"(gsrc));
}

__device__ __forceinline__ void cp_stage(uint32_t stage_base, int bm0, int bn0,
                                         int kt, int tid) {
    int k0 = kt * BK;
    uint32_t a_base = stage_base;
    uint32_t b_base = stage_base + BM * LDB;
#pragma unroll
    for (int i = 0; i < 2; i++) {
        int idx = tid + i * NTHR;
        int r = idx >> 2, c = idx & 3;
        cp16(a_base + r * LDB + c * 16,
             g_emb + (size_t)(bm0 + r) * Hd + k0 + c * 16);
    }
#pragma unroll
    for (int i = 0; i < 2; i++) {
        int idx = tid + i * NTHR;
        int r = idx >> 2, c = idx & 3;
        cp16(b_base + r * LDB + c * 16,
             g_w + (size_t)(bn0 + r) * Hd + k0 + c * 16);
    }
    asm volatile("cp.async.commit_group;\n" ::: "memory");
}

__device__ __forceinline__ void ldmx4(uint32_t addr, uint32_t& r0, uint32_t& r1,
                                      uint32_t& r2, uint32_t& r3) {
    asm volatile("ldmatrix.sync.aligned.m8n8.x4.shared.b16 {%0,%1,%2,%3}, [%4];"
                 : "=r"(r0), "=r"(r1), "=r"(r2), "=r"(r3) : "r"(addr));
}

__global__ __launch_bounds__(NTHR, 2) void gemm_fused(const int* __restrict__ labels) {
    extern __shared__ __align__(16) char smem[];
    __shared__ float rowacc[BM];
    __shared__ int slab[BM];

    int tid = threadIdx.x, wid = tid >> 5, lane = tid & 31;
    int bn0 = blockIdx.x * BN, bm0 = blockIdx.y * BM;
    int wm = (wid >> 2) * 64;       // 2 warp rows in M
    int wn = (wid & 3) * 32;        // 4 warp cols in N
    int fr = lane >> 2, fc = (lane & 3) * 2;

    if (tid < BM) {
        rowacc[tid] = 0.f;
        slab[tid] = labels[bm0 + tid];
    }

    uint32_t smem_base = (uint32_t)__cvta_generic_to_shared(smem);
    uint32_t aBase = smem_base + (wm + (lane & 15)) * LDB + ((lane >> 4) << 4);
    uint32_t bBase = smem_base + BM * LDB +
        (wn + ((lane >> 4) << 3) + (lane & 7)) * LDB + (((lane >> 3) & 1) << 4);

    uint32_t acc[4][4][2];
#pragma unroll
    for (int i = 0; i < 4; i++)
#pragma unroll
        for (int j = 0; j < 4; j++) {
            acc[i][j][0] = 0u;
            acc[i][j][1] = 0u;
        }

#pragma unroll
    for (int s = 0; s < NSTG - 1; s++)
        cp_stage(smem_base + s * STG_BYTES, bm0, bn0, s, tid);

#pragma unroll 1
    for (int kt = 0; kt < NKT; kt++) {
        asm volatile("cp.async.wait_group %0;\n" ::"n"(NSTG - 2) : "memory");
        __syncthreads();
        // Single barrier per kt: at iteration kt, all warps have finished
        // computing stage (kt-1)%NSTG (they passed this barrier), so the
        // refill below (targeting stage (kt+NSTG-1)%NSTG == (kt-1)%NSTG)
        // is safe without a bottom barrier.

        if (kt + NSTG - 1 < NKT)
            cp_stage(smem_base + ((kt + NSTG - 1) % NSTG) * STG_BYTES, bm0, bn0,
                     kt + NSTG - 1, tid);
        else
            asm volatile("cp.async.commit_group;\n" ::: "memory");

        uint32_t soff = (uint32_t)((kt % NSTG) * STG_BYTES);

#pragma unroll
        for (int ks = 0; ks < 2; ks++) {
            uint32_t a[4][4], b[4][2];
#pragma unroll
            for (int mi = 0; mi < 4; mi++)
                ldmx4(aBase + soff + mi * (16 * LDB) + ks * 32,
                      a[mi][0], a[mi][1], a[mi][2], a[mi][3]);
#pragma unroll
            for (int p = 0; p < 2; p++)
                ldmx4(bBase + soff + p * (16 * LDB) + ks * 32,
                      b[2 * p][0], b[2 * p][1], b[2 * p + 1][0], b[2 * p + 1][1]);
#pragma unroll
            for (int mi = 0; mi < 4; mi++)
#pragma unroll
                for (int ni = 0; ni < 4; ni++) {
                    uint32_t* c = acc[mi][ni];
                    asm volatile(
                        "mma.sync.aligned.m16n8k32.row.col.f16.e4m3.e4m3.f16 "
                        "{%0,%1}, {%2,%3,%4,%5}, {%6,%7}, {%0,%1};"
                        : "+r"(c[0]), "+r"(c[1])
                        : "r"(a[mi][0]), "r"(a[mi][1]), "r"(a[mi][2]), "r"(a[mi][3]),
                          "r"(b[ni][0]), "r"(b[ni][1]));
                }
        }
    }

    // ---- fused epilogue: arcface margin + shifted sum-exp ----
#pragma unroll
    for (int mi = 0; mi < 4; mi++) {
        int lr0 = wm + mi * 16 + fr;
        int lr1 = lr0 + 8;
        int lab0 = slab[lr0], lab1 = slab[lr1];
        float s0 = 0.f, s1 = 0.f;
#pragma unroll
        for (int ni = 0; ni < 4; ni++) {
            int gc = bn0 + wn + ni * 8 + fc;
            float2 lo = __half22float2(*(const __half2*)&acc[mi][ni][0]);
            float2 hi = __half22float2(*(const __half2*)&acc[mi][ni][1]);
            float cvals[4] = {lo.x, lo.y, hi.x, hi.y};
#pragma unroll
            for (int e = 0; e < 2; e++) {
                int col = gc + e;
                {
                    float cv = cvals[e] * INV_S2;
                    float lg = ARC_SCALE * cv - ARC_SCALE;
                    if (col == lab0) {
                        float sn = sqrtf(fmaxf(0.f, 1.f - cv * cv));
                        float phi = cv * COS_M - sn * SIN_M;
                        if (!(cv > TH_C)) phi = cv - MM_C;
                        lg = ARC_SCALE * phi - ARC_SCALE;
                        g_lablogit[bm0 + lr0] = ARC_SCALE * phi;
                    }
                    s0 += __expf(lg);
                }
                {
                    float cv = cvals[2 + e] * INV_S2;
                    float lg = ARC_SCALE * cv - ARC_SCALE;
                    if (col == lab1) {
                        float sn = sqrtf(fmaxf(0.f, 1.f - cv * cv));
                        float phi = cv * COS_M - sn * SIN_M;
                        if (!(cv > TH_C)) phi = cv - MM_C;
                        lg = ARC_SCALE * phi - ARC_SCALE;
                        g_lablogit[bm0 + lr1] = ARC_SCALE * phi;
                    }
                    s1 += __expf(lg);
                }
            }
        }
        s0 += __shfl_down_sync(0xffffffffu, s0, 1);
        s0 += __shfl_down_sync(0xffffffffu, s0, 2);
        s1 += __shfl_down_sync(0xffffffffu, s1, 1);
        s1 += __shfl_down_sync(0xffffffffu, s1, 2);
        if ((lane & 3) == 0) {
            atomicAdd(&rowacc[lr0], s0);
            atomicAdd(&rowacc[lr1], s1);
        }
    }
    __syncthreads();
    if (tid < BM) atomicAdd(&g_rowsum[bm0 + tid], rowacc[tid]);
}

// ---------------- K3: final mean over rows ----------------
__global__ __launch_bounds__(256) void finish_kernel(float* __restrict__ out) {
    __shared__ float sbuf[8];
    float s = 0.f;
    for (int i = threadIdx.x; i < NROWS; i += 256)
        s += ARC_SCALE + logf(g_rowsum[i]) - g_lablogit[i];
    float tot = blockReduceSum(s, sbuf);
    if (threadIdx.x == 0) out[0] = tot * (1.f / NROWS);
}

// ---------------- launch ----------------
extern "C" void kernel_launch(void* const* d_in, const int* in_sizes, int n_in,
                              void* d_out, int out_size) {
    const float* enc = (const float*)d_in[0];
    const float* gamma = (const float*)d_in[1];
    const float* beta = (const float*)d_in[2];
    const float* arc_w = (const float*)d_in[3];
    const int* heads = (const int*)d_in[4];
    const int* tails = (const int*)d_in[5];
    const int* labels = (const int*)d_in[6];
    float* out = (float*)d_out;

    static int configured = 0;
    if (!configured) {
        cudaFuncSetAttribute(gemm_fused, cudaFuncAttributeMaxDynamicSharedMemorySize,
                             DSMEM_BYTES);
        configured = 1;
    }

    prep_kernel<<<NROWS + NC, 256>>>(enc, gamma, beta, heads, tails, arc_w);
    gemm_fused<<<dim3(NC / BN, NROWS / BM), NTHR, DSMEM_BYTES>>>(labels);
    finish_kernel<<<1, 256>>>(out);
}

// round 15
// speedup vs baseline: 1.0853x; 1.0430x over previous
#include <cuda_runtime.h>
#include <cuda_bf16.h>
#include <cuda_fp16.h>
#include <cuda_fp8.h>
#include <cstdint>

// Problem constants
#define Bsz 16
#define Sq 2048
#define Hd 1024
#define NSP 64
#define NROWS (Bsz * NSP)      // 1024
#define NC 4096
#define ARC_SCALE 30.0f
#define COS_M 0.8775825618903728f
#define SIN_M 0.479425538604203f
#define TH_C (-0.8775825618903728f)
#define MM_C 0.2397127693021015f
#define LN_EPS 1e-7f
#define FP8_SCALE 16.0f
#define INV_S2 (1.0f / 256.0f)

// ---------------- scratch (no allocations allowed) ----------------
__device__ __nv_fp8_storage_t g_emb[NROWS * Hd];
__device__ __nv_fp8_storage_t g_w[NC * Hd];
__device__ float g_rowsum[NROWS];
__device__ float g_lablogit[NROWS];

// ---------------- reductions ----------------
__device__ __forceinline__ float blockReduceSum(float v, float* sbuf) {
    int lane = threadIdx.x & 31, wid = threadIdx.x >> 5;
#pragma unroll
    for (int o = 16; o; o >>= 1) v += __shfl_down_sync(0xffffffffu, v, o);
    if (lane == 0) sbuf[wid] = v;
    __syncthreads();
    if (wid == 0) {
        v = (lane < 8) ? sbuf[lane] : 0.f;
#pragma unroll
        for (int o = 4; o; o >>= 1) v += __shfl_down_sync(0xffffffffu, v, o);
        if (lane == 0) sbuf[0] = v;
    }
    __syncthreads();
    float r = sbuf[0];
    __syncthreads();
    return r;
}

__device__ __forceinline__ uchar4 pack_fp8x4(float a, float b, float c, float d) {
    uchar4 o;
    o.x = __nv_cvt_float_to_fp8(a, __NV_SATFINITE, __NV_E4M3);
    o.y = __nv_cvt_float_to_fp8(b, __NV_SATFINITE, __NV_E4M3);
    o.z = __nv_cvt_float_to_fp8(c, __NV_SATFINITE, __NV_E4M3);
    o.w = __nv_cvt_float_to_fp8(d, __NV_SATFINITE, __NV_E4M3);
    return o;
}

// ---------------- K1: fused prep (block-per-task, pipelined span loop) ------
__global__ __launch_bounds__(256) void prep_kernel(
    const float* __restrict__ enc, const float* __restrict__ gamma,
    const float* __restrict__ beta, const int* __restrict__ heads,
    const int* __restrict__ tails, const float* __restrict__ w) {
    __shared__ float sbuf[8];
    int tid = threadIdx.x;

    if (blockIdx.x < NROWS) {
        int row = blockIdx.x;
        int b = row >> 6;
        int head = heads[row], tail = tails[row];
        float inv_len = 1.f / (float)(tail - head);

        const float4* base = (const float4*)enc + (size_t)b * Sq * (Hd / 4) + tid;
        float4 acc = make_float4(0.f, 0.f, 0.f, 0.f);
        float4 v = base[(size_t)head * (Hd / 4)];
        for (int t = head + 1; t < tail; ++t) {
            float4 vn = base[(size_t)t * (Hd / 4)];
            acc.x += v.x; acc.y += v.y; acc.z += v.z; acc.w += v.w;
            v = vn;
        }
        acc.x += v.x; acc.y += v.y; acc.z += v.z; acc.w += v.w;

        float x0 = acc.x * inv_len, x1 = acc.y * inv_len;
        float x2 = acc.z * inv_len, x3 = acc.w * inv_len;

        float s1 = blockReduceSum(x0 + x1 + x2 + x3, sbuf);
        float s2 = blockReduceSum(x0 * x0 + x1 * x1 + x2 * x2 + x3 * x3, sbuf);
        float mu = s1 * (1.f / Hd);
        float var = s2 * (1.f / Hd) - mu * mu;
        float rs = rsqrtf(var + LN_EPS);

        float4 gm = ((const float4*)gamma)[tid];
        float4 bt = ((const float4*)beta)[tid];
        float y0 = (x0 - mu) * rs * gm.x + bt.x;
        float y1 = (x1 - mu) * rs * gm.y + bt.y;
        float y2 = (x2 - mu) * rs * gm.z + bt.z;
        float y3 = (x3 - mu) * rs * gm.w + bt.w;

        float s3 = blockReduceSum(y0 * y0 + y1 * y1 + y2 * y2 + y3 * y3, sbuf);
        float sc = FP8_SCALE / fmaxf(sqrtf(s3), 1e-12f);

        ((uchar4*)(g_emb + (size_t)row * Hd))[tid] =
            pack_fp8x4(y0 * sc, y1 * sc, y2 * sc, y3 * sc);
        if (tid == 0) g_rowsum[row] = 0.f;
    } else {
        int row = blockIdx.x - NROWS;
        float4 v = ((const float4*)w)[(size_t)row * (Hd / 4) + tid];
        float s = blockReduceSum(v.x * v.x + v.y * v.y + v.z * v.z + v.w * v.w, sbuf);
        float sc = FP8_SCALE / fmaxf(sqrtf(s), 1e-12f);
        ((uchar4*)(g_w + (size_t)row * Hd))[tid] =
            pack_fp8x4(v.x * sc, v.y * sc, v.z * sc, v.w * sc);
    }
}

// ---------------- K2: FP8 GEMM (f16 acc), BM=64 tiles, 3 CTAs/SM ------------
#define BM 64
#define BN 128
#define BK 64
#define LDB 80
#define NSTG 4
#define NKT (Hd / BK)          // 16
#define STG_BYTES ((BM + BN) * LDB)    // 15360
#define DSMEM_BYTES (NSTG * STG_BYTES) // 61440
#define NTHR 256

__device__ __forceinline__ void cp16(uint32_t smem_dst, const void* gsrc) {
    asm volatile("cp.async.cg.shared.global [%0], [%1], 16;\n" ::"r"(smem_dst), "l"(gsrc));
}

__device__ __forceinline__ void cp_stage(uint32_t stage_base, int bm0, int bn0,
                                         int kt, int tid) {
    int k0 = kt * BK;
    uint32_t a_base = stage_base;
    uint32_t b_base = stage_base + BM * LDB;
    {   // A: 64 rows x 4 16B chunks = 256
        int r = tid >> 2, c = tid & 3;
        cp16(a_base + r * LDB + c * 16,
             g_emb + (size_t)(bm0 + r) * Hd + k0 + c * 16);
    }
#pragma unroll
    for (int i = 0; i < 2; i++) {   // B: 128 rows x 4 chunks = 512
        int idx = tid + i * NTHR;
        int r = idx >> 2, c = idx & 3;
        cp16(b_base + r * LDB + c * 16,
             g_w + (size_t)(bn0 + r) * Hd + k0 + c * 16);
    }
    asm volatile("cp.async.commit_group;\n" ::: "memory");
}

__device__ __forceinline__ void ldmx4(uint32_t addr, uint32_t& r0, uint32_t& r1,
                                      uint32_t& r2, uint32_t& r3) {
    asm volatile("ldmatrix.sync.aligned.m8n8.x4.shared.b16 {%0,%1,%2,%3}, [%4];"
                 : "=r"(r0), "=r"(r1), "=r"(r2), "=r"(r3) : "r"(addr));
}

__global__ __launch_bounds__(NTHR, 3) void gemm_fused(const int* __restrict__ labels) {
    extern __shared__ __align__(16) char smem[];
    __shared__ float rowacc[BM];
    __shared__ int slab[BM];

    int tid = threadIdx.x, wid = tid >> 5, lane = tid & 31;
    int bn0 = blockIdx.x * BN, bm0 = blockIdx.y * BM;
    int wm = (wid >> 2) * 32;       // 2 warp rows in M (32 each)
    int wn = (wid & 3) * 32;        // 4 warp cols in N (32 each)
    int fr = lane >> 2, fc = (lane & 3) * 2;

    if (tid < BM) {
        rowacc[tid] = 0.f;
        slab[tid] = labels[bm0 + tid];
    }

    uint32_t smem_base = (uint32_t)__cvta_generic_to_shared(smem);
    uint32_t aBase = smem_base + (wm + (lane & 15)) * LDB + ((lane >> 4) << 4);
    uint32_t bBase = smem_base + BM * LDB +
        (wn + ((lane >> 4) << 3) + (lane & 7)) * LDB + (((lane >> 3) & 1) << 4);

    uint32_t acc[2][4][2];
#pragma unroll
    for (int i = 0; i < 2; i++)
#pragma unroll
        for (int j = 0; j < 4; j++) {
            acc[i][j][0] = 0u;
            acc[i][j][1] = 0u;
        }

#pragma unroll
    for (int s = 0; s < NSTG - 1; s++)
        cp_stage(smem_base + s * STG_BYTES, bm0, bn0, s, tid);

#pragma unroll 1
    for (int kt = 0; kt < NKT; kt++) {
        asm volatile("cp.async.wait_group %0;\n" ::"n"(NSTG - 2) : "memory");
        __syncthreads();

        if (kt + NSTG - 1 < NKT)
            cp_stage(smem_base + ((kt + NSTG - 1) % NSTG) * STG_BYTES, bm0, bn0,
                     kt + NSTG - 1, tid);
        else
            asm volatile("cp.async.commit_group;\n" ::: "memory");

        uint32_t soff = (uint32_t)((kt % NSTG) * STG_BYTES);

#pragma unroll
        for (int ks = 0; ks < 2; ks++) {
            uint32_t a[2][4], b[4][2];
#pragma unroll
            for (int mi = 0; mi < 2; mi++)
                ldmx4(aBase + soff + mi * (16 * LDB) + ks * 32,
                      a[mi][0], a[mi][1], a[mi][2], a[mi][3]);
#pragma unroll
            for (int p = 0; p < 2; p++)
                ldmx4(bBase + soff + p * (16 * LDB) + ks * 32,
                      b[2 * p][0], b[2 * p][1], b[2 * p + 1][0], b[2 * p + 1][1]);
#pragma unroll
            for (int mi = 0; mi < 2; mi++)
#pragma unroll
                for (int ni = 0; ni < 4; ni++) {
                    uint32_t* c = acc[mi][ni];
                    asm volatile(
                        "mma.sync.aligned.m16n8k32.row.col.f16.e4m3.e4m3.f16 "
                        "{%0,%1}, {%2,%3,%4,%5}, {%6,%7}, {%0,%1};"
                        : "+r"(c[0]), "+r"(c[1])
                        : "r"(a[mi][0]), "r"(a[mi][1]), "r"(a[mi][2]), "r"(a[mi][3]),
                          "r"(b[ni][0]), "r"(b[ni][1]));
                }
        }
    }

    // ---- fused epilogue: arcface margin + shifted sum-exp ----
#pragma unroll
    for (int mi = 0; mi < 2; mi++) {
        int lr0 = wm + mi * 16 + fr;
        int lr1 = lr0 + 8;
        int lab0 = slab[lr0], lab1 = slab[lr1];
        float s0 = 0.f, s1 = 0.f;
#pragma unroll
        for (int ni = 0; ni < 4; ni++) {
            int gc = bn0 + wn + ni * 8 + fc;
            float2 lo = __half22float2(*(const __half2*)&acc[mi][ni][0]);
            float2 hi = __half22float2(*(const __half2*)&acc[mi][ni][1]);
            float cvals[4] = {lo.x, lo.y, hi.x, hi.y};
#pragma unroll
            for (int e = 0; e < 2; e++) {
                int col = gc + e;
                {
                    float cv = cvals[e] * INV_S2;
                    float lg = ARC_SCALE * cv - ARC_SCALE;
                    if (col == lab0) {
                        float sn = sqrtf(fmaxf(0.f, 1.f - cv * cv));
                        float phi = cv * COS_M - sn * SIN_M;
                        if (!(cv > TH_C)) phi = cv - MM_C;
                        lg = ARC_SCALE * phi - ARC_SCALE;
                        g_lablogit[bm0 + lr0] = ARC_SCALE * phi;
                    }
                    s0 += __expf(lg);
                }
                {
                    float cv = cvals[2 + e] * INV_S2;
                    float lg = ARC_SCALE * cv - ARC_SCALE;
                    if (col == lab1) {
                        float sn = sqrtf(fmaxf(0.f, 1.f - cv * cv));
                        float phi = cv * COS_M - sn * SIN_M;
                        if (!(cv > TH_C)) phi = cv - MM_C;
                        lg = ARC_SCALE * phi - ARC_SCALE;
                        g_lablogit[bm0 + lr1] = ARC_SCALE * phi;
                    }
                    s1 += __expf(lg);
                }
            }
        }
        s0 += __shfl_down_sync(0xffffffffu, s0, 1);
        s0 += __shfl_down_sync(0xffffffffu, s0, 2);
        s1 += __shfl_down_sync(0xffffffffu, s1, 1);
        s1 += __shfl_down_sync(0xffffffffu, s1, 2);
        if ((lane & 3) == 0) {
            atomicAdd(&rowacc[lr0], s0);
            atomicAdd(&rowacc[lr1], s1);
        }
    }
    __syncthreads();
    if (tid < BM) atomicAdd(&g_rowsum[bm0 + tid], rowacc[tid]);
}

// ---------------- K3: final mean over rows ----------------
__global__ __launch_bounds__(256) void finish_kernel(float* __restrict__ out) {
    __shared__ float sbuf[8];
    float s = 0.f;
    for (int i = threadIdx.x; i < NROWS; i += 256)
        s += ARC_SCALE + logf(g_rowsum[i]) - g_lablogit[i];
    float tot = blockReduceSum(s, sbuf);
    if (threadIdx.x == 0) out[0] = tot * (1.f / NROWS);
}

// ---------------- launch ----------------
extern "C" void kernel_launch(void* const* d_in, const int* in_sizes, int n_in,
                              void* d_out, int out_size) {
    const float* enc = (const float*)d_in[0];
    const float* gamma = (const float*)d_in[1];
    const float* beta = (const float*)d_in[2];
    const float* arc_w = (const float*)d_in[3];
    const int* heads = (const int*)d_in[4];
    const int* tails = (const int*)d_in[5];
    const int* labels = (const int*)d_in[6];
    float* out = (float*)d_out;

    static int configured = 0;
    if (!configured) {
        cudaFuncSetAttribute(gemm_fused, cudaFuncAttributeMaxDynamicSharedMemorySize,
                             DSMEM_BYTES);
        configured = 1;
    }

    prep_kernel<<<NROWS + NC, 256>>>(enc, gamma, beta, heads, tails, arc_w);
    gemm_fused<<<dim3(NC / BN, NROWS / BM), NTHR, DSMEM_BYTES>>>(labels);
    finish_kernel<<<1, 256>>>(out);
}